// round 2
// baseline (speedup 1.0000x reference)
#include <cuda_runtime.h>
#include <cstdint>

#define T_STEPS 64
#define B_ENV   128
#define L_TOK   64
#define E_DIM   256
#define H_DIM   32
#define N_TOT   (T_STEPS * B_ENV)   // 8192

// ---- device-global scratch (no runtime allocation allowed) ----
__device__ float g_M[E_DIM * E_DIM];        // M = Wq^T Wk
__device__ float g_WeffT[E_DIM * E_DIM];    // WeffT[j][f] = sum_e Wout[f,e] Wv[e,j]
__device__ float g_wihT[E_DIM * 4 * H_DIM]; // w_ih transposed [e][g]
__device__ float g_bias[4 * H_DIM];         // b_ih + b_hh
__device__ float g_hidden[(size_t)N_TOT * E_DIM];  // 8 MB
__device__ float g_xg[(size_t)N_TOT * 4 * H_DIM];  // 4 MB
__device__ int   g_mask_mode;                       // 0=int32, 1=uint8, 2=float32
__device__ float g_df[(size_t)N_TOT * L_TOK];       // dropped flags (1.0 = dropped)

// =====================================================================
// Mask dtype detection + expansion (robust to int32 / uint8 / float32)
// =====================================================================
__global__ void detect_mask_kernel(const void* __restrict__ mask) {
    __shared__ int s_f32, s_gt1;
    if (threadIdx.x == 0) { s_f32 = 0; s_gt1 = 0; }
    __syncthreads();
    const unsigned* w = (const unsigned*)mask;
    // Scan 4096 words (16 KB) — safely within the smallest possible buffer
    // (uint8: 512 KB). Bool data as 0/1 bytes or 0/1 ints can never produce
    // 0x3F800000; fp32 1.0 always does (mask has ~50% ones in first rows).
    int f32 = 0, gt1 = 0;
    for (int i = threadIdx.x; i < 4096; i += blockDim.x) {
        unsigned v = w[i];
        if (v == 0x3F800000u) f32 = 1;
        if (v > 1u) gt1 = 1;
    }
    if (f32) atomicOr(&s_f32, 1);
    if (gt1) atomicOr(&s_gt1, 1);
    __syncthreads();
    if (threadIdx.x == 0)
        g_mask_mode = s_f32 ? 2 : (s_gt1 ? 1 : 0);
}

__global__ void expand_mask_kernel(const void* __restrict__ mask) {
    int i = blockIdx.x * 256 + threadIdx.x;  // N_TOT * L_TOK = 524288
    int mode = g_mask_mode;
    bool attend;
    if (mode == 0)      attend = ((const int*)mask)[i] != 0;
    else if (mode == 1) attend = ((const uint8_t*)mask)[i] != 0;
    else                attend = ((const float*)mask)[i] != 0.f;
    g_df[i] = attend ? 0.f : 1.f;
}

// =====================================================================
// Prep kernels (tiny, run once per launch)
// =====================================================================
__global__ void prep_M(const float* __restrict__ ipw) {
    int i = blockIdx.x, j = threadIdx.x;
    float acc = 0.f;
#pragma unroll 8
    for (int e = 0; e < E_DIM; e++)
        acc += ipw[e * E_DIM + i] * ipw[(E_DIM + e) * E_DIM + j];
    g_M[i * E_DIM + j] = acc;
}

__global__ void prep_Weff(const float* __restrict__ ipw, const float* __restrict__ opw) {
    int j = blockIdx.x, f = threadIdx.x;
    float acc = 0.f;
#pragma unroll 8
    for (int e = 0; e < E_DIM; e++)
        acc += opw[f * E_DIM + e] * ipw[(2 * E_DIM + e) * E_DIM + j];
    g_WeffT[j * E_DIM + f] = acc;
}

__global__ void prep_wih(const float* __restrict__ wih,
                         const float* __restrict__ bih,
                         const float* __restrict__ bhh) {
    int idx = blockIdx.x * 256 + threadIdx.x;  // 32768 total
    int g = idx / E_DIM, e = idx % E_DIM;
    g_wihT[e * 128 + g] = wih[idx];
    if (idx < 128) g_bias[idx] = bih[idx] + bhh[idx];
}

// =====================================================================
// Attention kernel: one block per sample n.
//   scores = (x M x^T)/16, softmax, colsum -> wgt
//   hidden = (wgt^T x) @ WeffT
// =====================================================================
#define XS_STRIDE 66     // x transposed [256][66]  (pad: conflict-free + 8B align)
#define TS_STRIDE 264    // t = x@M     [64][264]   (pad: float4-aligned rows)
#define SC_STRIDE 66     // scores      [64][66]

#define OFF_XS 0
#define OFF_TS (256 * XS_STRIDE)                 // 16896
#define OFF_SC (OFF_TS + 64 * TS_STRIDE)         // 33792
#define OFF_WG (OFF_SC + 64 * SC_STRIDE)         // 38016
#define OFF_XW (OFF_WG + 64)                     // 38080
#define OFF_DF (OFF_XW + 256)                    // 38336
#define SMEM_FLOATS (OFF_DF + 64)                // 38400 -> 153600 B

__global__ void __launch_bounds__(256) attn_kernel(const float* __restrict__ x) {
    extern __shared__ float sm[];
    float* xsT = sm + OFF_XS;
    float* ts  = sm + OFF_TS;
    float* sc  = sm + OFF_SC;
    float* wgt = sm + OFF_WG;
    float* xw  = sm + OFF_XW;
    float* df  = sm + OFF_DF;

    const int n   = blockIdx.x;
    const int tid = threadIdx.x;
    const float* xb = x + (size_t)n * (L_TOK * E_DIM);

    // ---- load x transposed: xsT[j][l] ----
    for (int idx = tid; idx < L_TOK * E_DIM; idx += 256) {
        int l = idx >> 8, j = idx & 255;
        xsT[j * XS_STRIDE + l] = xb[idx];
    }
    if (tid < 64) {
        df[tid]  = g_df[(size_t)n * L_TOK + tid];  // dropped flag
        wgt[tid] = 0.f;
    }
    __syncthreads();

    // ---- phase 2: ts[l][j] = sum_i xsT[i][l] * M[i][j]  (packed f32x2, l-pairs) ----
    {
        const int jg = tid & 31, lg = tid >> 5;
        const int j0 = jg * 8, l0 = lg * 8;
        unsigned long long acc[4][8];
#pragma unroll
        for (int p = 0; p < 4; p++)
#pragma unroll
            for (int q = 0; q < 8; q++) acc[p][q] = 0ull;

        const float* Mp = g_M + j0;
#pragma unroll 4
        for (int i = 0; i < E_DIM; i++) {
            const unsigned long long* xrow =
                (const unsigned long long*)(xsT + i * XS_STRIDE + l0);
            unsigned long long a0 = xrow[0], a1 = xrow[1], a2 = xrow[2], a3 = xrow[3];
            float4 b0 = *(const float4*)(Mp + i * E_DIM);
            float4 b1 = *(const float4*)(Mp + i * E_DIM + 4);
            float bs[8] = {b0.x, b0.y, b0.z, b0.w, b1.x, b1.y, b1.z, b1.w};
#pragma unroll
            for (int q = 0; q < 8; q++) {
                unsigned long long bb;
                asm("mov.b64 %0, {%1, %1};" : "=l"(bb) : "f"(bs[q]));
                asm("fma.rn.f32x2 %0, %1, %2, %0;" : "+l"(acc[0][q]) : "l"(a0), "l"(bb));
                asm("fma.rn.f32x2 %0, %1, %2, %0;" : "+l"(acc[1][q]) : "l"(a1), "l"(bb));
                asm("fma.rn.f32x2 %0, %1, %2, %0;" : "+l"(acc[2][q]) : "l"(a2), "l"(bb));
                asm("fma.rn.f32x2 %0, %1, %2, %0;" : "+l"(acc[3][q]) : "l"(a3), "l"(bb));
            }
        }
#pragma unroll
        for (int p = 0; p < 4; p++)
#pragma unroll
            for (int q = 0; q < 8; q++) {
                float lo, hi;
                asm("mov.b64 {%0, %1}, %2;" : "=f"(lo), "=f"(hi) : "l"(acc[p][q]));
                ts[(l0 + 2 * p)     * TS_STRIDE + j0 + q] = lo;
                ts[(l0 + 2 * p + 1) * TS_STRIDE + j0 + q] = hi;
            }
    }
    __syncthreads();

    // ---- scores: sc[lq][lk] = (sum_j ts[lq][j] * xsT[j][lk]) / 16 ----
    {
        const int tx = tid & 15, ty = tid >> 4;
        const int lk0 = tx * 4, lq0 = ty * 4;
        unsigned long long acc[4][2];
#pragma unroll
        for (int c = 0; c < 4; c++) { acc[c][0] = 0ull; acc[c][1] = 0ull; }

#pragma unroll 2
        for (int j = 0; j < E_DIM; j++) {
            const unsigned long long* krow =
                (const unsigned long long*)(xsT + j * XS_STRIDE + lk0);
            unsigned long long kk0 = krow[0], kk1 = krow[1];
#pragma unroll
            for (int c = 0; c < 4; c++) {
                float tv = ts[(lq0 + c) * TS_STRIDE + j];
                unsigned long long tt;
                asm("mov.b64 %0, {%1, %1};" : "=l"(tt) : "f"(tv));
                asm("fma.rn.f32x2 %0, %1, %2, %0;" : "+l"(acc[c][0]) : "l"(tt), "l"(kk0));
                asm("fma.rn.f32x2 %0, %1, %2, %0;" : "+l"(acc[c][1]) : "l"(tt), "l"(kk1));
            }
        }
        const float scale = 0.0625f;  // 1/sqrt(256)
#pragma unroll
        for (int c = 0; c < 4; c++)
#pragma unroll
            for (int p = 0; p < 2; p++) {
                float lo, hi;
                asm("mov.b64 {%0, %1}, %2;" : "=f"(lo), "=f"(hi) : "l"(acc[c][p]));
                sc[(lq0 + c) * SC_STRIDE + lk0 + 2 * p]     = lo * scale;
                sc[(lq0 + c) * SC_STRIDE + lk0 + 2 * p + 1] = hi * scale;
            }
    }
    __syncthreads();

    // ---- softmax per row + column-sum weights ----
    {
        const int w = tid >> 5, lane = tid & 31;
        const bool dk0 = df[lane] > 0.5f, dk1 = df[lane + 32] > 0.5f;
        float wacc0 = 0.f, wacc1 = 0.f;
#pragma unroll
        for (int r = 0; r < 8; r++) {
            int lq = w * 8 + r;
            bool dq = df[lq] > 0.5f;
            float s0 = sc[lq * SC_STRIDE + lane];
            float s1 = sc[lq * SC_STRIDE + lane + 32];
            if (dq && dk0) s0 = -1e30f;
            if (dq && dk1) s1 = -1e30f;
            float m = fmaxf(s0, s1);
#pragma unroll
            for (int o = 16; o; o >>= 1) m = fmaxf(m, __shfl_xor_sync(0xffffffffu, m, o));
            float e0 = __expf(s0 - m), e1 = __expf(s1 - m);
            float ssum = e0 + e1;
#pragma unroll
            for (int o = 16; o; o >>= 1) ssum += __shfl_xor_sync(0xffffffffu, ssum, o);
            float inv = 1.f / ssum;
            wacc0 += e0 * inv;
            wacc1 += e1 * inv;
        }
        atomicAdd(&wgt[lane], wacc0);
        atomicAdd(&wgt[lane + 32], wacc1);
    }
    __syncthreads();

    // ---- xw[j] = sum_k wgt[k] * x[k][j] ----
    {
        float acc = 0.f;
#pragma unroll 8
        for (int k = 0; k < L_TOK; k++)
            acc += wgt[k] * xsT[tid * XS_STRIDE + k];
        xw[tid] = acc;
    }
    __syncthreads();

    // ---- hidden[f] = sum_j xw[j] * WeffT[j][f] ----
    {
        float acc = 0.f;
        const float* Wp = g_WeffT + tid;
#pragma unroll 8
        for (int j = 0; j < E_DIM; j++)
            acc += xw[j] * Wp[(size_t)j * E_DIM];
        g_hidden[(size_t)n * E_DIM + tid] = acc;
    }
}

// =====================================================================
// xg = hidden @ w_ih^T + (b_ih + b_hh) : one block per 8 rows
// =====================================================================
__global__ void __launch_bounds__(256) gates_in_kernel() {
    __shared__ float hsm[8 * E_DIM];
    const int n0 = blockIdx.x * 8;
    const int tid = threadIdx.x;
    for (int idx = tid; idx < 8 * E_DIM; idx += 256)
        hsm[idx] = g_hidden[(size_t)n0 * E_DIM + idx];
    __syncthreads();

    const int g = tid & 127, half = tid >> 7;
    float acc[4];
    float bz = g_bias[g];
#pragma unroll
    for (int r = 0; r < 4; r++) acc[r] = bz;

#pragma unroll 4
    for (int e = 0; e < E_DIM; e++) {
        float wv = g_wihT[e * 128 + g];
#pragma unroll
        for (int r = 0; r < 4; r++)
            acc[r] += wv * hsm[(half + 2 * r) * E_DIM + e];
    }
#pragma unroll
    for (int r = 0; r < 4; r++)
        g_xg[(size_t)(n0 + half + 2 * r) * 128 + g] = acc[r];
}

// =====================================================================
// LSTM scan + critic. Each warp owns ONE env (b): h,c register-resident,
// shfl-broadcast recurrence. 16 blocks x 8 warps = 128 envs.
// =====================================================================
__device__ __forceinline__ float sigmoidf_(float v) {
    return 1.f / (1.f + __expf(-v));
}

__global__ void __launch_bounds__(256) lstm_kernel(const float* __restrict__ done,
                                                   const float* __restrict__ h0,
                                                   const float* __restrict__ c0,
                                                   const float* __restrict__ whh,
                                                   const float* __restrict__ cw,
                                                   const float* __restrict__ cb,
                                                   float* __restrict__ out) {
    __shared__ float whs[32 * 128];  // whs[m][g] = w_hh[g][m]
    const int tid = threadIdx.x, lane = tid & 31, w = tid >> 5;
    const int b = blockIdx.x * 8 + w;

    for (int idx = tid; idx < 4096; idx += 256) {
        int g = idx >> 5, m = idx & 31;
        whs[m * 128 + g] = whh[idx];
    }
    __syncthreads();

    float h = h0[b * H_DIM + lane];
    float c = c0[b * H_DIM + lane];
    const float cwv = cw[lane];
    const float cbv = cb[0];

    for (int t = 0; t < T_STEPS; t++) {
        const int n = t * B_ENV + b;
        const float keep = 1.f - done[n];
        h *= keep;
        c *= keep;
        const float* xgp = g_xg + (size_t)n * 128;
        float ai = xgp[lane];
        float af = xgp[32 + lane];
        float ag = xgp[64 + lane];
        float ao = xgp[96 + lane];
#pragma unroll
        for (int m = 0; m < 32; m++) {
            float hv = __shfl_sync(0xffffffffu, h, m);
            ai += hv * whs[m * 128 + lane];
            af += hv * whs[m * 128 + 32 + lane];
            ag += hv * whs[m * 128 + 64 + lane];
            ao += hv * whs[m * 128 + 96 + lane];
        }
        float gi = sigmoidf_(ai);
        float gf = sigmoidf_(af);
        float gg = tanhf(ag);
        float go = sigmoidf_(ao);
        c = gf * c + gi * gg;
        h = go * tanhf(c);

        float pv = h * cwv;
#pragma unroll
        for (int o = 16; o; o >>= 1) pv += __shfl_xor_sync(0xffffffffu, pv, o);
        if (lane == 0) out[n] = pv + cbv;
    }
}

// =====================================================================
// kernel_launch
// =====================================================================
extern "C" void kernel_launch(void* const* d_in, const int* in_sizes, int n_in,
                              void* d_out, int out_size) {
    const float* x    = (const float*)d_in[0];
    const float* done = (const float*)d_in[1];
    const void*  mask = d_in[2];
    const float* h0   = (const float*)d_in[3];
    const float* c0   = (const float*)d_in[4];
    const float* ipw  = (const float*)d_in[5];
    const float* opw  = (const float*)d_in[6];
    const float* wih  = (const float*)d_in[7];
    const float* whh  = (const float*)d_in[8];
    const float* bih  = (const float*)d_in[9];
    const float* bhh  = (const float*)d_in[10];
    const float* cw   = (const float*)d_in[11];
    const float* cb   = (const float*)d_in[12];
    float*       out  = (float*)d_out;

    (void)in_sizes; (void)n_in; (void)out_size;

    static_assert(SMEM_FLOATS * 4 == 153600, "smem layout");
    cudaFuncSetAttribute(attn_kernel, cudaFuncAttributeMaxDynamicSharedMemorySize,
                         SMEM_FLOATS * 4);

    detect_mask_kernel<<<1, 256>>>(mask);
    expand_mask_kernel<<<(N_TOT * L_TOK) / 256, 256>>>(mask);
    prep_M<<<E_DIM, E_DIM>>>(ipw);
    prep_Weff<<<E_DIM, E_DIM>>>(ipw, opw);
    prep_wih<<<128, 256>>>(wih, bih, bhh);
    attn_kernel<<<N_TOT, 256, SMEM_FLOATS * 4>>>(x);
    gates_in_kernel<<<N_TOT / 8, 256>>>();
    lstm_kernel<<<16, 256>>>(done, h0, c0, whh, cw, cb, out);
}